// round 10
// baseline (speedup 1.0000x reference)
#include <cuda_runtime.h>
#include <cuda_fp16.h>
#include <cstdint>

// ---------------------------------------------------------------------------
// PAC transposed conv via warp-level tensor cores (mma.sync, baseline PTX).
// R9: nb-outer (acc[2][4] only), kern premultiplied into B operand, B via
// ldmatrix.x4 (2 k-blocks per LDSM). No spills, 1 CTA/SM.
// For output (h,w): valid taps (kh,kw) have (h+kh) odd & (w+kw) odd.
// Per tap t, shift (di,dj)=(kh>>1,kw>>1):
//   D[o,px] += sum_c W[o,c,t] * (kern_t[px] * x[c, qy+di, qx+dj])
//   out[o, 2qy+cy, 2qx+cx] = bias[o] + D_{cy,cx}[o,px]
// kern_t = exp(-0.5*sum_g (guide[g,h+kh-1,w+kw-1]-guide[g,h,w])^2), 0-pad.
// CTA tile: 8x16 quads (px = qy*16+qx, 128 px), o = 64. 512 CTAs.
// ---------------------------------------------------------------------------

constexpr int SMX = 0;                    // X: [y 9][x 17][72 halves] rows 144B
constexpr int SMW = 22048;                // W: 9 taps x [64 o][72 halves]
constexpr int SMK = SMW + 9 * 9216;       // kern: [9 taps][128 px] fp32
constexpr int SMEM_TOTAL = SMK + 1152 * 4;   // 109600 B

__device__ __forceinline__ uint32_t s2u(const void* p) {
    uint32_t a;
    asm("{ .reg .u64 t; cvta.to.shared.u64 t, %1; cvt.u32.u64 %0, t; }"
        : "=r"(a) : "l"(p));
    return a;
}
__device__ __forceinline__ void ldmx4(uint32_t* r, uint32_t addr) {
    asm volatile("ldmatrix.sync.aligned.m8n8.x4.shared.b16 {%0,%1,%2,%3}, [%4];"
                 : "=r"(r[0]), "=r"(r[1]), "=r"(r[2]), "=r"(r[3]) : "r"(addr));
}
__device__ __forceinline__ void mma16816(float& d0, float& d1, float& d2, float& d3,
                                         const uint32_t* a, uint32_t b0, uint32_t b1) {
    asm volatile(
        "mma.sync.aligned.m16n8k16.row.col.f32.f16.f16.f32 "
        "{%0,%1,%2,%3}, {%4,%5,%6,%7}, {%8,%9}, {%0,%1,%2,%3};"
        : "+f"(d0), "+f"(d1), "+f"(d2), "+f"(d3)
        : "r"(a[0]), "r"(a[1]), "r"(a[2]), "r"(a[3]), "r"(b0), "r"(b1));
}
__device__ __forceinline__ uint32_t hmul2u(uint32_t a, uint32_t b) {
    __half2 r = __hmul2(*(__half2*)&a, *(__half2*)&b);
    return *(uint32_t*)&r;
}

__global__ void __launch_bounds__(512)
pac_hmma(const float* __restrict__ x, const float* __restrict__ g,
         const float* __restrict__ wgt, const float* __restrict__ bias,
         float* __restrict__ out)
{
    extern __shared__ char sm[];
    const uint32_t smb = s2u(sm);
    const int tid = threadIdx.x;

    const int b   = blockIdx.x >> 7;     // 4 batches
    const int tl  = blockIdx.x & 127;
    const int Ty0 = (tl >> 3) * 8;       // quad-row origin (tile 8 rows)
    const int Tx0 = (tl & 7) * 16;       // quad-col origin (tile 16 cols)

    // --- stage X: [y 0..8][x 0..16][64 c] fp16, 144B rows, zero halo
    const float* xb = x + b * 64 * 128 * 128;
    for (int i = tid; i < 153 * 32; i += 512) {
        int xc = i % 17;
        int yc = i / 17;
        int y  = yc % 9, c2 = yc / 9;
        int gy = Ty0 + y, gx = Tx0 + xc;
        __half2 v = __floats2half2_rn(0.f, 0.f);
        if (gy < 128 && gx < 128)
            v = __floats2half2_rn(xb[((2 * c2) * 128 + gy) * 128 + gx],
                                  xb[((2 * c2 + 1) * 128 + gy) * 128 + gx]);
        *(__half2*)(sm + SMX + (y * 17 + xc) * 144 + c2 * 4) = v;
    }
    // --- stage W: 9 taps x [64 o][64 c] fp16, 144B rows
    for (int i = tid; i < 9 * 64 * 32; i += 512) {
        int t  = i >> 11;
        int rm = i & 2047;
        int o  = rm >> 5, c2 = rm & 31;
        __half2 v = __floats2half2_rn(wgt[((2 * c2) * 64 + o) * 9 + t],
                                      wgt[((2 * c2 + 1) * 64 + o) * 9 + t]);
        *(__half2*)(sm + SMW + t * 9216 + o * 144 + c2 * 4) = v;
    }
    // --- stage kern: [tap 9][px 128] fp32
    {
        const float* gb = g + b * 3 * 65536;
        float* kernS = (float*)(sm + SMK);
        for (int v = tid; v < 1152; v += 512) {
            int t  = v >> 7, px = v & 127;
            int qy = px >> 4, qx = px & 15;
            int kh = t / 3, kw = t - kh * 3;
            int cy = 1 - (kh & 1), cx = 1 - (kw & 1);
            int h  = 2 * (Ty0 + qy) + cy;
            int w  = 2 * (Tx0 + qx) + cx;
            int yy = h + kh - 1, xx = w + kw - 1;
            bool inb = ((unsigned)yy < 256u) & ((unsigned)xx < 256u);
            float s = 0.f;
            #pragma unroll
            for (int gg = 0; gg < 3; ++gg) {
                float gc = __ldg(&gb[gg * 65536 + h * 256 + w]);
                float gn = inb ? __ldg(&gb[gg * 65536 + yy * 256 + xx]) : 0.f;
                float d = gn - gc;
                s = fmaf(d, d, s);
            }
            kernS[v] = __expf(-0.5f * s);
        }
    }
    __syncthreads();

    // warp tiling: mblk -> 16 o rows ; nq -> 32 px (2 quad-rows)
    const int wid  = tid >> 5, lane = tid & 31;
    const int mblk = wid >> 2, nq = wid & 3;
    const int ob   = mblk * 16;
    const int gq   = lane >> 2, t4 = lane & 3;   // D rows gq,gq+8; cols 2t4,2t4+1

    // A ldmatrix lane address (row-major A, x4: rows|rows+8 x 2 k-halves)
    const int a_orow = ob + (lane & 7) + ((lane >> 3) & 1) * 8;
    const uint32_t aoff = smb + SMW + (uint32_t)(a_orow * 144 + (lane >> 4) * 16);
    // B ldmatrix x4 lane address: rows = px (bj), bmat = k-half, kpair = kb odd
    const int bj    = lane & 7;
    const int bmat  = (lane >> 3) & 1;
    const int kpair = (lane >> 4) & 1;
    const float* kernS = (const float*)(sm + SMK);

    const float bias_lo = __ldg(&bias[ob + gq]);
    const float bias_hi = __ldg(&bias[ob + gq + 8]);
    float* obase = out + (size_t)b * 64 * 65536;

    #pragma unroll
    for (int nb = 0; nb < 4; ++nb) {
        const int qy  = 2 * nq + (nb >> 1);
        const int qx8 = (nb & 1) * 8;
        const uint32_t bbase =
            smb + SMX + (uint32_t)((qy * 17 + qx8 + bj) * 144 + bmat * 16 + kpair * 32);
        const float* kpn = kernS + qy * 16 + qx8 + (lane >> 2);

        #pragma unroll
        for (int grp = 0; grp < 2; ++grp) {
            float acc[2][4];
            #pragma unroll
            for (int c2 = 0; c2 < 2; ++c2)
                #pragma unroll
                for (int e = 0; e < 4; ++e) acc[c2][e] = 0.f;

            const int ntap = grp ? 6 : 3;
            #pragma unroll
            for (int j = 0; j < 6; ++j) {
                if (j >= ntap) break;
                const int kh = grp == 0 ? 1 : (j < 3 ? 0 : 2);
                const int kw = j % 3;
                const int t  = kh * 3 + kw;
                const int cxi = 1 - (kw & 1);
                const uint32_t doff = (uint32_t)((((kh >> 1) * 17) + (kw >> 1)) * 144);
                const uint32_t ab = aoff + (uint32_t)(t * 9216);

                __half2 hv = __float2half2_rn(kpn[t * 128]);
                const uint32_t kh2 = *(const uint32_t*)&hv;

                #pragma unroll
                for (int kp2 = 0; kp2 < 2; ++kp2) {
                    uint32_t A0[4], A1[4], B[4];
                    ldmx4(A0, ab + (uint32_t)(kp2 * 64));
                    ldmx4(A1, ab + (uint32_t)(kp2 * 64 + 32));
                    ldmx4(B, bbase + doff + (uint32_t)(kp2 * 64));
                    B[0] = hmul2u(B[0], kh2);
                    B[1] = hmul2u(B[1], kh2);
                    B[2] = hmul2u(B[2], kh2);
                    B[3] = hmul2u(B[3], kh2);
                    mma16816(acc[cxi][0], acc[cxi][1], acc[cxi][2], acc[cxi][3],
                             A0, B[0], B[1]);
                    mma16816(acc[cxi][0], acc[cxi][1], acc[cxi][2], acc[cxi][3],
                             A1, B[2], B[3]);
                }
            }

            // store strip (nb, cy=grp): 2 o rows x 4 consecutive w
            const int h  = 2 * (Ty0 + qy) + grp;
            const int w0 = 2 * (Tx0 + qx8 + 2 * t4);
            #pragma unroll
            for (int rh = 0; rh < 2; ++rh) {
                const int o  = ob + gq + rh * 8;
                const float bv = rh ? bias_hi : bias_lo;
                float4 v = make_float4(acc[0][rh * 2]     + bv,
                                       acc[1][rh * 2]     + bv,
                                       acc[0][rh * 2 + 1] + bv,
                                       acc[1][rh * 2 + 1] + bv);
                *(float4*)&obase[((size_t)o * 256 + h) * 256 + w0] = v;
            }
        }
    }
}

extern "C" void kernel_launch(void* const* d_in, const int* in_sizes, int n_in,
                              void* d_out, int out_size) {
    const float* x      = (const float*)d_in[0];
    const float* guide  = (const float*)d_in[1];
    const float* weight = (const float*)d_in[2];
    const float* bias   = (const float*)d_in[3];
    float* out = (float*)d_out;

    cudaFuncSetAttribute(pac_hmma, cudaFuncAttributeMaxDynamicSharedMemorySize,
                         SMEM_TOTAL);
    // 4 batches * 128 tiles (8x16 quads each) = 512 CTAs
    pac_hmma<<<512, 512, SMEM_TOTAL>>>(x, guide, weight, bias, out);
}

// round 11
// speedup vs baseline: 3.1808x; 3.1808x over previous
#include <cuda_runtime.h>
#include <cuda_fp16.h>
#include <cstdint>

// ---------------------------------------------------------------------------
// PAC transposed conv via warp-level tensor cores (mma.sync, baseline PTX).
// R10: runtime (non-unrolled) kh loop to kill unroll-induced spills,
//      coalesced W staging (linear LDG + scatter STS, padded tap stride),
//      kern premultiplied into B, A fragments shared across nb.
// For output (h,w): valid taps (kh,kw) have (h+kh) odd & (w+kw) odd.
// Per tap t, shift (di,dj)=(kh>>1,kw>>1):
//   D[o,px] += sum_c W[o,c,t] * (kern_t[px] * x[c, qy+di, qx+dj])
//   out[o, 2qy+cy, 2qx+cx] = bias[o] + D_{cy,cx}[o,px]
// kern_t = exp(-0.5*sum_g (guide[g,h+kh-1,w+kw-1]-guide[g,h,w])^2), 0-pad.
// CTA tile: 8x16 quads (px = qy*16+qx, 128 px), o = 64. 512 CTAs.
// ---------------------------------------------------------------------------

constexpr int SMX  = 0;                   // X: [y9][x17] rows of 144B = 22032
constexpr int SMW  = 22032;               // W: 9 taps, padded stride
constexpr int TAPS = 9360;                // 65*144: tap t at bank shift 4t
constexpr int SMK  = SMW + 9 * TAPS;      // 106272 ; kern [9][128] fp32
constexpr int SMEM_TOTAL = SMK + 1152 * 4;   // 110880 B

__device__ __forceinline__ uint32_t s2u(const void* p) {
    uint32_t a;
    asm("{ .reg .u64 t; cvta.to.shared.u64 t, %1; cvt.u32.u64 %0, t; }"
        : "=r"(a) : "l"(p));
    return a;
}
__device__ __forceinline__ void ldmx4(uint32_t* r, uint32_t addr) {
    asm volatile("ldmatrix.sync.aligned.m8n8.x4.shared.b16 {%0,%1,%2,%3}, [%4];"
                 : "=r"(r[0]), "=r"(r[1]), "=r"(r[2]), "=r"(r[3]) : "r"(addr));
}
__device__ __forceinline__ void ldmx2(uint32_t& r0, uint32_t& r1, uint32_t addr) {
    asm volatile("ldmatrix.sync.aligned.m8n8.x2.shared.b16 {%0,%1}, [%2];"
                 : "=r"(r0), "=r"(r1) : "r"(addr));
}
__device__ __forceinline__ void mma16816(float& d0, float& d1, float& d2, float& d3,
                                         const uint32_t* a, uint32_t b0, uint32_t b1) {
    asm volatile(
        "mma.sync.aligned.m16n8k16.row.col.f32.f16.f16.f32 "
        "{%0,%1,%2,%3}, {%4,%5,%6,%7}, {%8,%9}, {%0,%1,%2,%3};"
        : "+f"(d0), "+f"(d1), "+f"(d2), "+f"(d3)
        : "r"(a[0]), "r"(a[1]), "r"(a[2]), "r"(a[3]), "r"(b0), "r"(b1));
}
__device__ __forceinline__ uint32_t hmul2u(uint32_t a, uint32_t b) {
    __half2 r = __hmul2(*(__half2*)&a, *(__half2*)&b);
    return *(uint32_t*)&r;
}

__global__ void __launch_bounds__(512)
pac_hmma(const float* __restrict__ x, const float* __restrict__ g,
         const float* __restrict__ wgt, const float* __restrict__ bias,
         float* __restrict__ out)
{
    extern __shared__ char sm[];
    const uint32_t smb = s2u(sm);
    const int tid = threadIdx.x;

    const int b   = blockIdx.x >> 7;     // 4 batches
    const int tl  = blockIdx.x & 127;
    const int Ty0 = (tl >> 3) * 8;       // quad-row origin (tile 8 rows)
    const int Tx0 = (tl & 7) * 16;       // quad-col origin (tile 16 cols)

    // --- stage X: [y 0..8][x 0..16][64 c] fp16, 144B rows, zero halo
    const float* xb = x + b * 64 * 128 * 128;
    for (int i = tid; i < 153 * 32; i += 512) {
        int xc = i % 17;
        int yc = i / 17;
        int y  = yc % 9, c2 = yc / 9;
        int gy = Ty0 + y, gx = Tx0 + xc;
        __half2 v = __floats2half2_rn(0.f, 0.f);
        if (gy < 128 && gx < 128)
            v = __floats2half2_rn(xb[((2 * c2) * 128 + gy) * 128 + gx],
                                  xb[((2 * c2 + 1) * 128 + gy) * 128 + gx]);
        *(__half2*)(sm + SMX + (y * 17 + xc) * 144 + c2 * 4) = v;
    }
    // --- stage W: linear (coalesced) read, scatter STS.16 into [t][o][c]
    for (int i = tid; i < 36864; i += 512) {
        int t  = i % 9;
        int oc = i / 9;
        int o  = oc & 63, c = oc >> 6;
        *(__half*)(sm + SMW + t * TAPS + o * 144 + c * 2) =
            __float2half_rn(wgt[i]);
    }
    // --- stage kern: [tap 9][px 128] fp32
    {
        const float* gb = g + b * 3 * 65536;
        float* kernS = (float*)(sm + SMK);
        for (int v = tid; v < 1152; v += 512) {
            int t  = v >> 7, px = v & 127;
            int qy = px >> 4, qx = px & 15;
            int kh = t / 3, kw = t - kh * 3;
            int cy = 1 - (kh & 1), cx = 1 - (kw & 1);
            int h  = 2 * (Ty0 + qy) + cy;
            int w  = 2 * (Tx0 + qx) + cx;
            int yy = h + kh - 1, xx = w + kw - 1;
            bool inb = ((unsigned)yy < 256u) & ((unsigned)xx < 256u);
            float s = 0.f;
            #pragma unroll
            for (int gg = 0; gg < 3; ++gg) {
                float gc = __ldg(&gb[gg * 65536 + h * 256 + w]);
                float gn = inb ? __ldg(&gb[gg * 65536 + yy * 256 + xx]) : 0.f;
                float d = gn - gc;
                s = fmaf(d, d, s);
            }
            kernS[v] = __expf(-0.5f * s);
        }
    }
    __syncthreads();

    // warp tiling: mblk -> 16 o rows ; nq -> 32 px (2 quad-rows)
    const int wid  = tid >> 5, lane = tid & 31;
    const int mblk = wid >> 2, nq = wid & 3;
    const int ob   = mblk * 16;
    const int gq   = lane >> 2, t4 = lane & 3;   // D rows gq,gq+8; cols 2t4,2t4+1

    // A ldmatrix lane address (row-major A, x4: o rows | o+8 rows, 2 k-halves)
    const int a_orow = ob + (lane & 7) + ((lane >> 3) & 1) * 8;
    const uint32_t aoff = smb + SMW + (uint32_t)(a_orow * 144 + (lane >> 4) * 16);
    // B ldmx2 lane address pieces
    const int bj   = lane & 7;
    const int bmat = (lane >> 3) & 1;
    // B base for nb=0 (nb adds compile-time constants)
    const uint32_t bbase0 =
        smb + SMX + (uint32_t)(((2 * nq) * 17 + bj) * 144 + bmat * 16);
    const float* kbase = (const float*)(sm + SMK) + nq * 32 + (lane >> 2);

    const float bias_lo = __ldg(&bias[ob + gq]);
    const float bias_hi = __ldg(&bias[ob + gq + 8]);
    float* obase = out + (size_t)b * 64 * 65536;

    #pragma unroll
    for (int grp = 0; grp < 2; ++grp) {
        float acc[2][16];
        #pragma unroll
        for (int c2 = 0; c2 < 2; ++c2)
            #pragma unroll
            for (int e = 0; e < 16; ++e) acc[c2][e] = 0.f;

        const int kh0 = grp ? 0 : 1;
        const int khs = grp ? 2 : 3;

        #pragma unroll
        for (int kw = 0; kw < 3; ++kw) {
            const int cxi = 1 - (kw & 1);     // compile-time
            const int dj  = kw >> 1;          // compile-time

            #pragma unroll 1
            for (int kh = kh0; kh < 3; kh += khs) {
                const int t  = kh * 3 + kw;
                const int di = kh >> 1;
                const uint32_t ab = aoff + (uint32_t)(t * TAPS);
                const uint32_t bd = bbase0 + (uint32_t)((di * 17 + dj) * 144);
                const float* kt = kbase + t * 128;

                // kern (fp32 -> dup half2) per nb
                uint32_t kh2[4];
                #pragma unroll
                for (int nb = 0; nb < 4; ++nb) {
                    __half2 hv = __float2half2_rn(kt[(nb >> 1) * 16 + (nb & 1) * 8]);
                    kh2[nb] = *(uint32_t*)&hv;
                }

                #pragma unroll
                for (int kb = 0; kb < 4; ++kb) {
                    uint32_t A[4];
                    ldmx4(A, ab + (uint32_t)(kb * 32));
                    #pragma unroll
                    for (int nb = 0; nb < 4; ++nb) {
                        const uint32_t bofs =
                            (uint32_t)(((nb >> 1) * 17 + (nb & 1) * 8) * 144 + kb * 32);
                        uint32_t b0, b1;
                        ldmx2(b0, b1, bd + bofs);
                        b0 = hmul2u(b0, kh2[nb]);
                        b1 = hmul2u(b1, kh2[nb]);
                        mma16816(acc[cxi][nb * 4 + 0], acc[cxi][nb * 4 + 1],
                                 acc[cxi][nb * 4 + 2], acc[cxi][nb * 4 + 3],
                                 A, b0, b1);
                    }
                }
            }
        }

        // store strips for cy = grp
        #pragma unroll
        for (int nb = 0; nb < 4; ++nb) {
            const int qy = 2 * nq + (nb >> 1);
            const int qx = (nb & 1) * 8 + 2 * t4;
            const int h  = 2 * (Ty0 + qy) + grp;
            const int w0 = 2 * (Tx0 + qx);
            #pragma unroll
            for (int rh = 0; rh < 2; ++rh) {
                const int o  = ob + gq + rh * 8;
                const float bv = rh ? bias_hi : bias_lo;
                float4 v = make_float4(acc[0][nb * 4 + rh * 2]     + bv,
                                       acc[1][nb * 4 + rh * 2]     + bv,
                                       acc[0][nb * 4 + rh * 2 + 1] + bv,
                                       acc[1][nb * 4 + rh * 2 + 1] + bv);
                *(float4*)&obase[((size_t)o * 256 + h) * 256 + w0] = v;
            }
        }
    }
}

extern "C" void kernel_launch(void* const* d_in, const int* in_sizes, int n_in,
                              void* d_out, int out_size) {
    const float* x      = (const float*)d_in[0];
    const float* guide  = (const float*)d_in[1];
    const float* weight = (const float*)d_in[2];
    const float* bias   = (const float*)d_in[3];
    float* out = (float*)d_out;

    cudaFuncSetAttribute(pac_hmma, cudaFuncAttributeMaxDynamicSharedMemorySize,
                         SMEM_TOTAL);
    // 4 batches * 128 tiles (8x16 quads each) = 512 CTAs
    pac_hmma<<<512, 512, SMEM_TOTAL>>>(x, guide, weight, bias, out);
}